// round 6
// baseline (speedup 1.0000x reference)
#include <cuda_runtime.h>
#include <math_constants.h>
#include <cstdint>
#include <cstddef>

// ---------------------------------------------------------------------------
// Problem constants
// ---------------------------------------------------------------------------
#define BATCH   8
#define NMEDIA  8192
#define SLAT    64
#define HEADS   8
#define NSPLIT  33

// ---------------------------------------------------------------------------
// Scratch (device globals)
// ---------------------------------------------------------------------------
__device__ float    g_latproj[(size_t)512 * 1536];                  // [q | k | v]
__device__ float    g_kvmed [(size_t)BATCH * NMEDIA * 1024];
__device__ float    g_opart [(size_t)64 * NSPLIT * 64 * 64];
__device__ float    g_mpart [(size_t)64 * NSPLIT * 64];
__device__ float    g_lpart [(size_t)64 * NSPLIT * 64];
__device__ float    g_attno [(size_t)512 * 512];
__device__ uint32_t g_Wlat  [(size_t)1536 * 512];   // k-permuted tf32
__device__ uint32_t g_Wmed  [(size_t)1024 * 512];   // k-permuted tf32
__device__ uint32_t g_WoT   [(size_t)512 * 512];    // UNpermuted tf32
__device__ float    g_c1lat[1536], g_c2lat[1536];
__device__ float    g_c1med[1024], g_c2med[1024];

// ---------------------------------------------------------------------------
// Helpers
// ---------------------------------------------------------------------------
__device__ __forceinline__ uint32_t f2tf32(float x) {
    uint32_t r;
    asm("cvt.rna.tf32.f32 %0, %1;" : "=r"(r) : "f"(x));
    return r;
}

__device__ __forceinline__ void mma_tf32(float* c, const uint32_t* a, const uint32_t* b) {
    asm volatile(
        "mma.sync.aligned.m16n8k8.row.col.f32.tf32.tf32.f32 "
        "{%0,%1,%2,%3},{%4,%5,%6,%7},{%8,%9},{%0,%1,%2,%3};"
        : "+f"(c[0]), "+f"(c[1]), "+f"(c[2]), "+f"(c[3])
        : "r"(a[0]), "r"(a[1]), "r"(a[2]), "r"(a[3]), "r"(b[0]), "r"(b[1]));
}

__device__ __forceinline__ void cp16(void* smem, const void* gmem) {
    uint32_t a = (uint32_t)__cvta_generic_to_shared(smem);
    asm volatile("cp.async.cg.shared.global [%0], [%1], 16;" :: "r"(a), "l"(gmem));
}
#define CP_COMMIT() asm volatile("cp.async.commit_group;")
#define CP_WAIT0()  asm volatile("cp.async.wait_group 0;")

// slot permutation within each k-group of 8: slot(k) = (k%4)*2 + k/4
__device__ __forceinline__ int kperm(int k) {
    return (k & ~7) | (((k & 3) << 1) | ((k >> 2) & 1));
}

// ---------------------------------------------------------------------------
// Weight prep: transpose + g-fold + scale-fold + tf32 convert.
//  z=0: 0.125*g_l*Wq -> Wlat[0:512]    z=1: g_l*Wkv -> Wlat[512:1536]
//  z=2: g_m*Wkv -> Wmed                z=3: Wo -> WoT (no perm)
// z<3 are written with the k-slot permutation for LDS.64 fragment loads.
// ---------------------------------------------------------------------------
__global__ void __launch_bounds__(256)
prep_w(const float* __restrict__ Wq, const float* __restrict__ Wkv,
       const float* __restrict__ Wo, const float* __restrict__ gl,
       const float* __restrict__ gm)
{
    const float* W; uint32_t* WT; const float* gv; int nc; float scale = 1.f;
    bool perm = true;
    switch (blockIdx.z) {
        case 0:  W = Wq;  WT = g_Wlat;             gv = gl;      nc = 512;  scale = 0.125f; break;
        case 1:  W = Wkv; WT = g_Wlat + 512 * 512; gv = gl;      nc = 1024; break;
        case 2:  W = Wkv; WT = g_Wmed;             gv = gm;      nc = 1024; break;
        default: W = Wo;  WT = g_WoT;              gv = nullptr; nc = 512;  perm = false; break;
    }
    const int c0 = blockIdx.x * 64;
    if (c0 >= nc) return;
    const int k0 = blockIdx.y * 64;
    const int tid = threadIdx.x;

    __shared__ float ts[64][65];
    #pragma unroll
    for (int it = 0; it < 16; ++it) {
        int e = tid + it * 256;
        int k = e >> 6, c = e & 63;
        float gk = gv ? gv[k0 + k] * scale : scale;
        ts[k][c] = W[(size_t)(k0 + k) * nc + c0 + c] * gk;
    }
    __syncthreads();
    #pragma unroll
    for (int it = 0; it < 16; ++it) {
        int e = tid + it * 256;
        int c = e >> 6, k = e & 63;
        int kk = k0 + k;
        int kd = perm ? kperm(kk) : kk;
        WT[(size_t)(c0 + c) * 512 + kd] = f2tf32(ts[k][c]);
    }
}

// ---------------------------------------------------------------------------
// Column-vector prep (permutation-invariant colsum).
// ---------------------------------------------------------------------------
__global__ void __launch_bounds__(256)
prep_c(const float* __restrict__ Wq, const float* __restrict__ Wkv,
       const float* __restrict__ bq, const float* __restrict__ bkv,
       const float* __restrict__ bl, const float* __restrict__ bm)
{
    const int bx = blockIdx.x;
    const float *W, *bv, *bias;
    const uint32_t* WT;
    float *c1o, *c2o;
    int nc, srcCol, colBase;
    float scale = 1.f;

    if (bx < 24) {
        colBase = bx * 64;
        if (colBase < 512) { W = Wq;  nc = 512;  bias = bq;  srcCol = colBase;       scale = 0.125f; }
        else               { W = Wkv; nc = 1024; bias = bkv; srcCol = colBase - 512; }
        bv = bl; WT = g_Wlat; c1o = g_c1lat; c2o = g_c2lat;
    } else {
        colBase = (bx - 24) * 64;
        W = Wkv; nc = 1024; bias = bkv; srcCol = colBase;
        bv = bm; WT = g_Wmed; c1o = g_c1med; c2o = g_c2med;
    }

    const int tid = threadIdx.x;
    {
        const int c = tid & 63, kq = tid >> 6;
        float part = 0.f;
        for (int k = kq; k < 512; k += 4)
            part = fmaf(bv[k], W[(size_t)k * nc + srcCol + c], part);
        __shared__ float red[4][64];
        red[kq][c] = part;
        __syncthreads();
        if (tid < 64) {
            float s = red[0][tid] + red[1][tid] + red[2][tid] + red[3][tid];
            c2o[colBase + tid] = (s + bias[srcCol + tid]) * scale;
        }
    }
    {
        const int warp = tid >> 5, lane = tid & 31;
        #pragma unroll
        for (int cc = 0; cc < 8; ++cc) {
            int col = colBase + warp * 8 + cc;
            const uint32_t* p = WT + (size_t)col * 512;
            float s = 0.f;
            #pragma unroll
            for (int u = 0; u < 16; ++u)
                s += __uint_as_float(p[lane + 32 * u]);
            #pragma unroll
            for (int o = 16; o > 0; o >>= 1)
                s += __shfl_xor_sync(0xffffffffu, s, o);
            if (lane == 0) c1o[col] = s;
        }
    }
}

// ---------------------------------------------------------------------------
// Main GEMM: 128x128 tile, 256 threads (8 warps, 2x4, warp tile 64x32),
// 2 blocks/SM, double-buffered, k-permuted smem (stride 40, LDS.64 frags,
// conflict-free), in-kernel LN stats, epilogue LN: out = rs*acc - rs*mu*c1 + c2.
// Grid: [0,4096) media KV (mask-skipped), [4096,4144) latproj.
// ---------------------------------------------------------------------------
#define TSTR 40
#define TBUF (128 * TSTR)

__global__ void __launch_bounds__(256, 2)
gemm_tile(const float* __restrict__ x, const float* __restrict__ lat,
          const int* __restrict__ idx)
{
    const int bid = blockIdx.x;
    const float* src; const uint32_t* WT; float* out;
    const float *c1, *c2;
    int nc;
    if (bid < 4096) {
        const int b = bid >> 9, rr = (bid >> 3) & 63, cc = bid & 7;
        const int rowBase = rr * 128;
        if (rowBase >= idx[b] * 256) return;
        src = x + ((size_t)b * NMEDIA + rowBase) * 512;
        WT  = g_Wmed + (size_t)(cc * 128) * 512;
        out = g_kvmed + ((size_t)b * NMEDIA + rowBase) * 1024 + cc * 128;
        c1 = g_c1med + cc * 128; c2 = g_c2med + cc * 128;
        nc = 1024;
    } else {
        const int l = bid - 4096;        // 0..47
        const int rr = l / 12, cc = l % 12;
        src = lat + (size_t)(rr * 128) * 512;
        WT  = g_Wlat + (size_t)(cc * 128) * 512;
        out = g_latproj + (size_t)(rr * 128) * 1536 + cc * 128;
        c1 = g_c1lat + cc * 128; c2 = g_c2lat + cc * 128;
        nc = 1536;
    }

    extern __shared__ uint32_t dyn[];
    uint32_t* As = dyn;                  // [2][128*40]
    uint32_t* Bs = dyn + 2 * TBUF;       // [2][128*40]
    __shared__ float2 st[128];

    const int tid = threadIdx.x;
    const int am = tid >> 3, akq = (tid & 7) * 4;
    const int sbase = (akq & 24) | ((akq & 4) >> 2);   // permuted slot base

    float4 rv[4];
    float sm[4] = {0.f, 0.f, 0.f, 0.f};
    float sq[4] = {0.f, 0.f, 0.f, 0.f};

    auto lda = [&](int k0) {
        #pragma unroll
        for (int u = 0; u < 4; ++u)
            rv[u] = *(const float4*)(src + (size_t)(am + 32 * u) * 512 + k0 + akq);
    };
    auto sta = [&](int buf) {
        #pragma unroll
        for (int u = 0; u < 4; ++u) {
            float4 v = rv[u];
            sm[u] += v.x + v.y + v.z + v.w;
            sq[u] = fmaf(v.x, v.x, sq[u]); sq[u] = fmaf(v.y, v.y, sq[u]);
            sq[u] = fmaf(v.z, v.z, sq[u]); sq[u] = fmaf(v.w, v.w, sq[u]);
            uint32_t* dst = &As[buf * TBUF + (am + 32 * u) * TSTR + sbase];
            dst[0] = f2tf32(v.x);
            dst[2] = f2tf32(v.y);
            dst[4] = f2tf32(v.z);
            dst[6] = f2tf32(v.w);
        }
    };
    auto cpb = [&](int k0, int buf) {
        #pragma unroll
        for (int u = 0; u < 4; ++u) {
            int c = am + 32 * u;
            cp16(&Bs[buf * TBUF + c * TSTR + akq],
                 WT + (size_t)c * 512 + k0 + akq);
        }
        CP_COMMIT();
    };

    const int warp = tid >> 5, lane = tid & 31;
    const int wm = warp >> 2, wn = warp & 3;
    const int qr = lane >> 2, qc = lane & 3;

    float acc[4][4][4];
    #pragma unroll
    for (int i = 0; i < 4; ++i)
        #pragma unroll
        for (int j = 0; j < 4; ++j)
            #pragma unroll
            for (int r = 0; r < 4; ++r) acc[i][j][r] = 0.f;

    lda(0); sta(0); cpb(0, 0);

    for (int kc = 0; kc < 16; ++kc) {
        const int buf = kc & 1;
        CP_WAIT0();
        __syncthreads();

        const bool nxt = (kc < 15);
        if (nxt) { lda((kc + 1) * 32); cpb((kc + 1) * 32, buf ^ 1); }

        const uint32_t* Ab = As + buf * TBUF;
        const uint32_t* Bb = Bs + buf * TBUF;
        #pragma unroll
        for (int ks = 0; ks < 4; ++ks) {
            uint32_t a[4][4], bb[4][2];
            #pragma unroll
            for (int i = 0; i < 4; ++i) {
                int r0 = wm * 64 + i * 16 + qr;
                uint2 lo = *(const uint2*)&Ab[(r0    ) * TSTR + ks * 8 + 2 * qc];
                uint2 hi = *(const uint2*)&Ab[(r0 + 8) * TSTR + ks * 8 + 2 * qc];
                a[i][0] = lo.x; a[i][2] = lo.y;
                a[i][1] = hi.x; a[i][3] = hi.y;
            }
            #pragma unroll
            for (int j = 0; j < 4; ++j) {
                int cb = wn * 32 + j * 8 + qr;
                uint2 bv = *(const uint2*)&Bb[cb * TSTR + ks * 8 + 2 * qc];
                bb[j][0] = bv.x; bb[j][1] = bv.y;
            }
            #pragma unroll
            for (int i = 0; i < 4; ++i)
                #pragma unroll
                for (int j = 0; j < 4; ++j)
                    mma_tf32(acc[i][j], a[i], bb[j]);
        }

        if (nxt) sta(buf ^ 1);
    }

    // ---- LN stats reduce (8-lane groups share rows) ----
    #pragma unroll
    for (int u = 0; u < 4; ++u) {
        #pragma unroll
        for (int o = 1; o < 8; o <<= 1) {
            sm[u] += __shfl_xor_sync(0xffffffffu, sm[u], o);
            sq[u] += __shfl_xor_sync(0xffffffffu, sq[u], o);
        }
    }
    if ((tid & 7) == 0) {
        #pragma unroll
        for (int u = 0; u < 4; ++u) {
            float mu  = sm[u] * (1.f / 512.f);
            float var = fmaf(-mu, mu, sq[u] * (1.f / 512.f));
            st[am + 32 * u] = make_float2(mu, rsqrtf(var + 1e-5f));
        }
    }
    __syncthreads();

    // ---- epilogue: out = rs*acc - rs*mu*c1 + c2 ----
    #pragma unroll
    for (int i = 0; i < 4; ++i) {
        int r0 = wm * 64 + i * 16 + qr;
        float2 s0 = st[r0], s1 = st[r0 + 8];
        float rs0 = s0.y, t0 = s0.y * s0.x;
        float rs1 = s1.y, t1 = s1.y * s1.x;
        #pragma unroll
        for (int j = 0; j < 4; ++j) {
            int col = wn * 32 + j * 8 + qc * 2;
            float2 c1v = *(const float2*)(c1 + col);
            float2 c2v = *(const float2*)(c2 + col);
            float2 o0, o1;
            o0.x = fmaf(acc[i][j][0], rs0, fmaf(-t0, c1v.x, c2v.x));
            o0.y = fmaf(acc[i][j][1], rs0, fmaf(-t0, c1v.y, c2v.y));
            o1.x = fmaf(acc[i][j][2], rs1, fmaf(-t1, c1v.x, c2v.x));
            o1.y = fmaf(acc[i][j][3], rs1, fmaf(-t1, c1v.y, c2v.y));
            *(float2*)(out + (size_t)(r0    ) * nc + col) = o0;
            *(float2*)(out + (size_t)(r0 + 8) * nc + col) = o1;
        }
    }
}
#define TILE_SMEM (4 * TBUF * (int)sizeof(uint32_t))

// ---------------------------------------------------------------------------
// Output projection GEMM (R5-passing version, unpermuted WoT): 128x128 tile.
// ---------------------------------------------------------------------------
__global__ void __launch_bounds__(256, 2)
gemm_out(const float* __restrict__ src, const float* __restrict__ bias,
         float* __restrict__ out)
{
    const int rowBase = (blockIdx.x >> 2) * 128;
    const int colBase = (blockIdx.x & 3) * 128;
    const float* srcB = src + (size_t)rowBase * 512;
    float* outB = out + (size_t)rowBase * 512;

    extern __shared__ uint32_t dyn2[];
    uint32_t* As = dyn2;                 // [2][128*36]
    uint32_t* Bs = dyn2 + 2 * 4608;      // [2][128*36]

    const int tid = threadIdx.x;
    const int am = tid >> 3, akq = (tid & 7) * 4;
    float4 rv[4];

    auto lda = [&](int k0) {
        #pragma unroll
        for (int u = 0; u < 4; ++u)
            rv[u] = *(const float4*)(srcB + (size_t)(am + 32 * u) * 512 + k0 + akq);
    };
    auto sta = [&](int buf) {
        #pragma unroll
        for (int u = 0; u < 4; ++u) {
            float4 v = rv[u];
            uint4 t;
            t.x = f2tf32(v.x); t.y = f2tf32(v.y);
            t.z = f2tf32(v.z); t.w = f2tf32(v.w);
            *(uint4*)&As[buf * 4608 + (am + 32 * u) * 36 + akq] = t;
        }
    };
    auto cpb = [&](int k0, int buf) {
        #pragma unroll
        for (int u = 0; u < 4; ++u) {
            int c = am + 32 * u;
            cp16(&Bs[buf * 4608 + c * 36 + akq],
                 g_WoT + (size_t)(colBase + c) * 512 + k0 + akq);
        }
        CP_COMMIT();
    };

    const int warp = tid >> 5, lane = tid & 31;
    const int wm = warp >> 2, wn = warp & 3;
    const int qr = lane >> 2, qc = lane & 3;

    float acc[4][4][4];
    #pragma unroll
    for (int i = 0; i < 4; ++i)
        #pragma unroll
        for (int j = 0; j < 4; ++j)
            #pragma unroll
            for (int r = 0; r < 4; ++r) acc[i][j][r] = 0.f;

    lda(0); sta(0); cpb(0, 0);

    for (int kc = 0; kc < 16; ++kc) {
        const int buf = kc & 1;
        CP_WAIT0();
        __syncthreads();
        const bool nxt = (kc < 15);
        if (nxt) { lda((kc + 1) * 32); cpb((kc + 1) * 32, buf ^ 1); }

        const uint32_t* Ab = As + buf * 4608;
        const uint32_t* Bb = Bs + buf * 4608;
        #pragma unroll
        for (int ks = 0; ks < 4; ++ks) {
            uint32_t a[4][4], bb[4][2];
            #pragma unroll
            for (int i = 0; i < 4; ++i) {
                int r0 = wm * 64 + i * 16 + qr;
                a[i][0] = Ab[(r0    ) * 36 + ks * 8 + qc    ];
                a[i][1] = Ab[(r0 + 8) * 36 + ks * 8 + qc    ];
                a[i][2] = Ab[(r0    ) * 36 + ks * 8 + qc + 4];
                a[i][3] = Ab[(r0 + 8) * 36 + ks * 8 + qc + 4];
            }
            #pragma unroll
            for (int j = 0; j < 4; ++j) {
                int cb = wn * 32 + j * 8 + qr;
                bb[j][0] = Bb[cb * 36 + ks * 8 + qc    ];
                bb[j][1] = Bb[cb * 36 + ks * 8 + qc + 4];
            }
            #pragma unroll
            for (int i = 0; i < 4; ++i)
                #pragma unroll
                for (int j = 0; j < 4; ++j)
                    mma_tf32(acc[i][j], a[i], bb[j]);
        }
        if (nxt) sta(buf ^ 1);
    }

    #pragma unroll
    for (int i = 0; i < 4; ++i) {
        int r0 = wm * 64 + i * 16 + qr;
        #pragma unroll
        for (int j = 0; j < 4; ++j) {
            int col = colBase + wn * 32 + j * 8 + qc * 2;
            float2 bi = *(const float2*)(bias + col);
            *(float2*)(outB + (size_t)(r0    ) * 512 + col) =
                make_float2(acc[i][j][0] + bi.x, acc[i][j][1] + bi.y);
            *(float2*)(outB + (size_t)(r0 + 8) * 512 + col) =
                make_float2(acc[i][j][2] + bi.x, acc[i][j][3] + bi.y);
        }
    }
}
#define OUT_SMEM (4 * 4608 * (int)sizeof(uint32_t))

// ---------------------------------------------------------------------------
// Tensor-core split-KV flash attention (unchanged, passing).
// ---------------------------------------------------------------------------
__global__ void __launch_bounds__(128)
attn_split_tc(const float* __restrict__ latproj, const int* __restrict__ indices)
{
    const int b = blockIdx.z, h = blockIdx.y, s = blockIdx.x;
    const int vis = indices[b];
    const bool is_lat = (s == 32);
    if (!is_lat && s >= vis) return;

    extern __shared__ float smf[];
    float*    Ks = smf;                              // [64][72]
    float*    Vs = Ks + 64 * 72;                     // [64][72]
    uint32_t* Qs = (uint32_t*)(Vs + 64 * 72);        // [64][68]
    uint32_t* Ps = Qs + 64 * 68;                     // [64][68]

    const int tid = threadIdx.x, warp = tid >> 5, lane = tid & 31;
    const int qr = lane >> 2, qc = lane & 3;
    const int r0 = warp * 16 + qr;

    #pragma unroll
    for (int it = 0; it < 8; ++it) {
        int e = tid + it * 128;
        int r = e >> 4, cq = (e & 15) * 4;
        float4 v = *(const float4*)(latproj + ((size_t)b * 64 + r) * 1536 + h * 64 + cq);
        uint4 t;
        t.x = f2tf32(v.x); t.y = f2tf32(v.y);
        t.z = f2tf32(v.z); t.w = f2tf32(v.w);
        *(uint4*)&Qs[r * 68 + cq] = t;
    }

    const float* kvbase; int ldkv, koff, voff, nch;
    if (is_lat) {
        kvbase = latproj + (size_t)b * 64 * 1536;
        ldkv = 1536; koff = 512 + h * 64; voff = 1024 + h * 64; nch = 1;
    } else {
        kvbase = g_kvmed + ((size_t)b * NMEDIA + (size_t)s * 256) * 1024;
        ldkv = 1024; koff = h * 64; voff = 512 + h * 64; nch = 4;
    }

    float m0 = -CUDART_INF_F, m1 = -CUDART_INF_F, l0 = 0.f, l1 = 0.f;
    float o[8][4];
    #pragma unroll
    for (int nf = 0; nf < 8; ++nf)
        #pragma unroll
        for (int r = 0; r < 4; ++r) o[nf][r] = 0.f;

    for (int ch = 0; ch < nch; ++ch) {
        __syncthreads();
        #pragma unroll
        for (int it = 0; it < 8; ++it) {
            int e = tid + it * 128;
            int j = e >> 4, dq = (e & 15) * 4;
            const float* rp = kvbase + (size_t)(ch * 64 + j) * ldkv;
            float4 kv = *(const float4*)(rp + koff + dq);
            float4 vv = *(const float4*)(rp + voff + dq);
            uint32_t* kd = (uint32_t*)&Ks[j * 72 + dq];
            kd[0] = f2tf32(kv.x); kd[1] = f2tf32(kv.y);
            kd[2] = f2tf32(kv.z); kd[3] = f2tf32(kv.w);
            uint32_t* vd = (uint32_t*)&Vs[j * 72 + dq];
            vd[0] = f2tf32(vv.x); vd[1] = f2tf32(vv.y);
            vd[2] = f2tf32(vv.z); vd[3] = f2tf32(vv.w);
        }
        __syncthreads();

        float sacc[8][4] = {};
        const uint32_t* Ku = (const uint32_t*)Ks;
        #pragma unroll
        for (int ks = 0; ks < 8; ++ks) {
            uint32_t a[4];
            a[0] = Qs[(r0    ) * 68 + ks * 8 + qc    ];
            a[1] = Qs[(r0 + 8) * 68 + ks * 8 + qc    ];
            a[2] = Qs[(r0    ) * 68 + ks * 8 + qc + 4];
            a[3] = Qs[(r0 + 8) * 68 + ks * 8 + qc + 4];
            #pragma unroll
            for (int nf = 0; nf < 8; ++nf) {
                uint32_t bb[2];
                bb[0] = Ku[(nf * 8 + qr) * 72 + ks * 8 + qc    ];
                bb[1] = Ku[(nf * 8 + qr) * 72 + ks * 8 + qc + 4];
                mma_tf32(sacc[nf], a, bb);
            }
        }

        float rm0 = -CUDART_INF_F, rm1 = -CUDART_INF_F;
        #pragma unroll
        for (int nf = 0; nf < 8; ++nf) {
            rm0 = fmaxf(rm0, fmaxf(sacc[nf][0], sacc[nf][1]));
            rm1 = fmaxf(rm1, fmaxf(sacc[nf][2], sacc[nf][3]));
        }
        rm0 = fmaxf(rm0, __shfl_xor_sync(0xffffffffu, rm0, 1));
        rm0 = fmaxf(rm0, __shfl_xor_sync(0xffffffffu, rm0, 2));
        rm1 = fmaxf(rm1, __shfl_xor_sync(0xffffffffu, rm1, 1));
        rm1 = fmaxf(rm1, __shfl_xor_sync(0xffffffffu, rm1, 2));
        float mn0 = fmaxf(m0, rm0), mn1 = fmaxf(m1, rm1);
        float cc0 = __expf(m0 - mn0), cc1 = __expf(m1 - mn1);
        float s0 = 0.f, s1 = 0.f;
        #pragma unroll
        for (int nf = 0; nf < 8; ++nf) {
            float p00 = __expf(sacc[nf][0] - mn0);
            float p01 = __expf(sacc[nf][1] - mn0);
            float p10 = __expf(sacc[nf][2] - mn1);
            float p11 = __expf(sacc[nf][3] - mn1);
            s0 += p00 + p01; s1 += p10 + p11;
            *(uint2*)&Ps[(r0    ) * 68 + nf * 8 + qc * 2] =
                make_uint2(f2tf32(p00), f2tf32(p01));
            *(uint2*)&Ps[(r0 + 8) * 68 + nf * 8 + qc * 2] =
                make_uint2(f2tf32(p10), f2tf32(p11));
            o[nf][0] *= cc0; o[nf][1] *= cc0;
            o[nf][2] *= cc1; o[nf][3] *= cc1;
        }
        s0 += __shfl_xor_sync(0xffffffffu, s0, 1);
        s0 += __shfl_xor_sync(0xffffffffu, s0, 2);
        s1 += __shfl_xor_sync(0xffffffffu, s1, 1);
        s1 += __shfl_xor_sync(0xffffffffu, s1, 2);
        m0 = mn0; m1 = mn1;
        l0 = fmaf(l0, cc0, s0);
        l1 = fmaf(l1, cc1, s1);
        __syncwarp();

        const uint32_t* Vu = (const uint32_t*)Vs;
        #pragma unroll
        for (int ks = 0; ks < 8; ++ks) {
            uint32_t a[4];
            a[0] = Ps[(r0    ) * 68 + ks * 8 + qc    ];
            a[1] = Ps[(r0 + 8) * 68 + ks * 8 + qc    ];
            a[2] = Ps[(r0    ) * 68 + ks * 8 + qc + 4];
            a[3] = Ps[(r0 + 8) * 68 + ks * 8 + qc + 4];
            #pragma unroll
            for (int nf = 0; nf < 8; ++nf) {
                uint32_t bb[2];
                bb[0] = Vu[(ks * 8 + qc    ) * 72 + nf * 8 + qr];
                bb[1] = Vu[(ks * 8 + qc + 4) * 72 + nf * 8 + qr];
                mma_tf32(o[nf], a, bb);
            }
        }
    }

    const size_t pbase = ((size_t)(b * HEADS + h)) * NSPLIT + s;
    float* op = g_opart + pbase * 4096;
    #pragma unroll
    for (int nf = 0; nf < 8; ++nf) {
        *(float2*)&op[(r0    ) * 64 + nf * 8 + qc * 2] = make_float2(o[nf][0], o[nf][1]);
        *(float2*)&op[(r0 + 8) * 64 + nf * 8 + qc * 2] = make_float2(o[nf][2], o[nf][3]);
    }
    if (qc == 0) {
        g_mpart[pbase * 64 + r0    ] = m0;
        g_mpart[pbase * 64 + r0 + 8] = m1;
        g_lpart[pbase * 64 + r0    ] = l0;
        g_lpart[pbase * 64 + r0 + 8] = l1;
    }
}
#define ATTN_SMEM ((2 * 64 * 72 + 2 * 64 * 68) * (int)sizeof(float))

// ---------------------------------------------------------------------------
// Combine split partials -> attn_out.
// ---------------------------------------------------------------------------
__global__ void __launch_bounds__(256)
attn_combine(const int* __restrict__ indices, float* __restrict__ attn_out)
{
    const int bh = blockIdx.x;
    const int b = bh >> 3, h = bh & 7;
    const int vis = indices[b];
    const int warp = threadIdx.x >> 5, lane = threadIdx.x & 31;
    const int i = blockIdx.y * 8 + warp;

    __shared__ float ws[8][33];
    __shared__ float linv[8];

    const size_t base = (size_t)bh * NSPLIT;

    float m    = (lane < vis) ? g_mpart[(base + lane) * 64 + i] : -CUDART_INF_F;
    float mlat = g_mpart[(base + 32) * 64 + i];
    float mm = fmaxf(m, mlat);
    #pragma unroll
    for (int o = 16; o > 0; o >>= 1)
        mm = fmaxf(mm, __shfl_xor_sync(0xffffffffu, mm, o));

    float w  = (lane < vis) ? __expf(m - mm) : 0.f;
    float wl = __expf(mlat - mm);
    float l  = (lane < vis) ? g_lpart[(base + lane) * 64 + i] * w : 0.f;
    #pragma unroll
    for (int o = 16; o > 0; o >>= 1)
        l += __shfl_xor_sync(0xffffffffu, l, o);
    float ll = g_lpart[(base + 32) * 64 + i] * wl;

    ws[warp][lane] = w;
    if (lane == 0) {
        ws[warp][32] = wl;
        linv[warp] = 1.f / (l + ll);
    }
    __syncwarp();

    const int d = lane * 2;
    float2 v = *(const float2*)(g_opart + (base + 32) * 4096 + i * 64 + d);
    float a0 = v.x * ws[warp][32];
    float a1 = v.y * ws[warp][32];
    for (int s = 0; s < vis; ++s) {
        float wv = ws[warp][s];
        float2 u = *(const float2*)(g_opart + (base + s) * 4096 + i * 64 + d);
        a0 = fmaf(u.x, wv, a0);
        a1 = fmaf(u.y, wv, a1);
    }
    float li = linv[warp];
    *(float2*)(attn_out + ((size_t)b * 64 + i) * 512 + h * 64 + d) =
        make_float2(a0 * li, a1 * li);
}

// ---------------------------------------------------------------------------
// Launch
// ---------------------------------------------------------------------------
extern "C" void kernel_launch(void* const* d_in, const int* in_sizes, int n_in,
                              void* d_out, int out_size)
{
    (void)in_sizes; (void)n_in; (void)out_size;
    const float* x    = (const float*)d_in[0];
    const float* lat  = (const float*)d_in[1];
    const int*   idx  = (const int*)  d_in[2];
    const float* g_m  = (const float*)d_in[3];
    const float* b_m  = (const float*)d_in[4];
    const float* g_l  = (const float*)d_in[5];
    const float* b_l  = (const float*)d_in[6];
    const float* Wq   = (const float*)d_in[7];
    const float* bq   = (const float*)d_in[8];
    const float* Wkv  = (const float*)d_in[9];
    const float* bkv  = (const float*)d_in[10];
    const float* Wo   = (const float*)d_in[11];
    const float* bo   = (const float*)d_in[12];
    float* out = (float*)d_out;

    void *plp, *pattno;
    cudaGetSymbolAddress(&plp,    g_latproj);
    cudaGetSymbolAddress(&pattno, g_attno);

    cudaFuncSetAttribute(gemm_tile,
                         cudaFuncAttributeMaxDynamicSharedMemorySize, TILE_SMEM);
    cudaFuncSetAttribute(gemm_out,
                         cudaFuncAttributeMaxDynamicSharedMemorySize, OUT_SMEM);
    cudaFuncSetAttribute(attn_split_tc,
                         cudaFuncAttributeMaxDynamicSharedMemorySize, ATTN_SMEM);

    // weight + column-vector prep
    prep_w<<<dim3(16, 8, 4), 256>>>(Wq, Wkv, Wo, g_l, g_m);
    prep_c<<<40, 256>>>(Wq, Wkv, bq, bkv, b_l, b_m);

    // unified media-KV + latent projections (LN fused via epilogue)
    gemm_tile<<<4144, 256, TILE_SMEM>>>(x, lat, idx);

    // attention
    attn_split_tc<<<dim3(NSPLIT, HEADS, BATCH), 128, ATTN_SMEM>>>(
        (const float*)plp, idx);
    attn_combine<<<dim3(64, 8), 256>>>(idx, (float*)pattno);

    // output projection
    gemm_out<<<16, 256, OUT_SMEM>>>((const float*)pattno, bo, out);
}